// round 9
// baseline (speedup 1.0000x reference)
#include <cuda_runtime.h>
#include <math.h>

#define NN 17
#define DD 512
#define HH 8
#define MM 256
#define CIN 515

typedef unsigned long long u64;

// ---------------- f32x2 helpers ----------------
__device__ __forceinline__ void ffma2(u64& acc, u64 a, u64 b) {
    asm("fma.rn.f32x2 %0, %1, %2, %0;" : "+l"(acc) : "l"(a), "l"(b));
}
__device__ __forceinline__ u64 dup2(float x) {
    u64 r; asm("mov.b64 %0, {%1, %1};" : "=l"(r) : "f"(x)); return r;
}
__device__ __forceinline__ u64 pack2(float x, float y) {
    u64 r; asm("mov.b64 %0, {%1, %2};" : "=l"(r) : "f"(x), "f"(y)); return r;
}
__device__ __forceinline__ float2 unpack2(u64 a) {
    float2 f; asm("mov.b64 {%0, %1}, %2;" : "=f"(f.x), "=f"(f.y) : "l"(a)); return f;
}

// ---------------- device scratch ----------------
__device__ float g_pA[32][HH][NN][DD];   // Xs@FC partials, 32 d-chunks (16 wide)
__device__ float g_f[HH][NN][DD];        // f = relu(Xs@FC)
__device__ float g_pB[64][HH][NN][MM];   // cat@W1 partials, 64 c-chunks (8 wide)
__device__ u64   g_hdnp[HH][MM][9];      // tanh hidden, dup-pair packed [m][(n,n+1)]
__device__ float g_out[NN * DD];         // conv accumulation (zero-init, reset each call)
__device__ int   g_ctr = 0;

// ================= Kernel A: partial f = Xs @ FC =================
// grid (dc=32, ec=2, h=8) = 512 blocks x 256 thr.
// Group g = tid>>7: g0 computes n 0..8, g1 computes n 9..16 (same e-pairs).
__global__ void __launch_bounds__(256) kA(const float* __restrict__ Xs,
                                          const float* __restrict__ FC) {
    const int dc = blockIdx.x, ec = blockIdx.y, h = blockIdx.z, tid = threadIdx.x;
    const int d0 = dc * 16;
    const int g = tid >> 7;
    const int P = ec * 128 + (tid & 127);   // e-pair index

    __shared__ __align__(16) u64 xsd[2][16][10];   // dup pairs [grp][dd][slot]
    for (int idx = tid; idx < 16 * 20; idx += 256) {
        int dd = idx / 20, s = idx % 20;
        int gg = s / 10, j = s % 10;
        int n = gg ? 9 + j : j;
        bool ok = gg ? (j < 8) : (j < 9);
        float v = ok ? Xs[n * DD + d0 + dd] : 0.f;
        xsd[gg][dd][j] = dup2(v);
    }
    __syncthreads();

    u64 acc[10];
#pragma unroll
    for (int j = 0; j < 10; ++j) acc[j] = 0ull;

    const u64* fc = reinterpret_cast<const u64*>(FC)
                  + (size_t)h * 131072 + (size_t)d0 * 256 + P;
    u64 buf[8];
#pragma unroll
    for (int p = 0; p < 8; ++p) buf[p] = fc[(size_t)p * 256];

#pragma unroll
    for (int dd = 0; dd < 16; ++dd) {
        u64 w = buf[dd & 7];
        if (dd < 8) buf[dd & 7] = fc[(size_t)(dd + 8) * 256];
        const ulonglong2* row = reinterpret_cast<const ulonglong2*>(&xsd[g][dd][0]);
#pragma unroll
        for (int j = 0; j < 5; ++j) {
            ulonglong2 q = row[j];
            ffma2(acc[2 * j],     q.x, w);
            ffma2(acc[2 * j + 1], q.y, w);
        }
    }
    if (g == 0) {
#pragma unroll
        for (int j = 0; j < 9; ++j)
            *reinterpret_cast<u64*>(&g_pA[dc][h][j][2 * P]) = acc[j];
    } else {
#pragma unroll
        for (int j = 0; j < 8; ++j)
            *reinterpret_cast<u64*>(&g_pA[dc][h][9 + j][2 * P]) = acc[j];
    }
}

// ================= Kernel B: reduce f chunk + relu, partial cat @ W1 =================
// grid (cc=64, h=8) = 512 blocks x 256 thr. Group split over n like kA.
// cc==63 additionally handles the 3 coordinate rows.
__global__ void __launch_bounds__(256) kB(const float* __restrict__ ROIs,
                                          const float* __restrict__ W1) {
    const int cc = blockIdx.x, h = blockIdx.y, tid = threadIdx.x;
    const int c0 = cc * 8;
    const int g = tid >> 7;
    const int mp = tid & 127;   // m-pair

    __shared__ __align__(16) u64 catd[2][11][10];   // rows 0..7 c, 8..10 coords

    for (int idx = tid; idx < 2 * 11 * 10; idx += 256)
        reinterpret_cast<u64*>(catd)[idx] = 0ull;
    __syncthreads();

    if (tid < NN * 8) {
        int n = tid >> 3, cp = tid & 7;
        float v = 0.f;
#pragma unroll
        for (int s = 0; s < 32; ++s) v += g_pA[s][h][n][c0 + cp];
        v = fmaxf(v, 0.f);
        g_f[h][n][c0 + cp] = v;
        if (n < 9) catd[0][cp][n] = dup2(v);
        else       catd[1][cp][n - 9] = dup2(v);
    }
    if (cc == 63 && tid < NN * 3) {
        int n = tid / 3, jj = tid % 3;
        float v = ROIs[tid];
        if (n < 9) catd[0][8 + jj][n] = dup2(v);
        else       catd[1][8 + jj][n - 9] = dup2(v);
    }
    __syncthreads();

    u64 acc[10];
#pragma unroll
    for (int j = 0; j < 10; ++j) acc[j] = 0ull;

    const u64* w1 = reinterpret_cast<const u64*>(W1)
                  + (size_t)h * 65920 + (size_t)c0 * 128 + mp;
    u64 buf[8];
#pragma unroll
    for (int p = 0; p < 8; ++p) buf[p] = w1[(size_t)p * 128];

#pragma unroll
    for (int i = 0; i < 8; ++i) {
        u64 w = buf[i];
        const ulonglong2* row = reinterpret_cast<const ulonglong2*>(&catd[g][i][0]);
#pragma unroll
        for (int j = 0; j < 5; ++j) {
            ulonglong2 q = row[j];
            ffma2(acc[2 * j],     q.x, w);
            ffma2(acc[2 * j + 1], q.y, w);
        }
    }
    if (cc == 63) {
#pragma unroll
        for (int jj = 0; jj < 3; ++jj) {
            u64 w = reinterpret_cast<const u64*>(W1)[(size_t)h * 65920 + (size_t)(DD + jj) * 128 + mp];
            const ulonglong2* row = reinterpret_cast<const ulonglong2*>(&catd[g][8 + jj][0]);
#pragma unroll
            for (int j = 0; j < 5; ++j) {
                ulonglong2 q = row[j];
                ffma2(acc[2 * j],     q.x, w);
                ffma2(acc[2 * j + 1], q.y, w);
            }
        }
    }
    if (g == 0) {
#pragma unroll
        for (int j = 0; j < 9; ++j)
            *reinterpret_cast<u64*>(&g_pB[cc][h][j][2 * mp]) = acc[j];
    } else {
#pragma unroll
        for (int j = 0; j < 8; ++j)
            *reinterpret_cast<u64*>(&g_pB[cc][h][9 + j][2 * mp]) = acc[j];
    }
}

// ================= Kernel C1: reduce g_pB + bias + tanh -> packed g_hdnp =================
// grid (mc=8, h=8) = 64 blocks x 256 thr; block handles 32 m's of head h.
__global__ void __launch_bounds__(256) kC1(const float* __restrict__ b1) {
    const int mc = blockIdx.x, h = blockIdx.y, tid = threadIdx.x;
    const int m0 = mc * 32;

    __shared__ float hdnf[32][20];   // [local m][n], col 17 = pad

    if (tid < NN * 8) {
        int n = tid >> 3, q = tid & 7;
        int m4 = m0 + q * 4;
        float4 s = *reinterpret_cast<const float4*>(b1 + h * MM + m4);
#pragma unroll
        for (int cc = 0; cc < 64; ++cc) {
            float4 v = *reinterpret_cast<const float4*>(&g_pB[cc][h][n][m4]);
            s.x += v.x; s.y += v.y; s.z += v.z; s.w += v.w;
        }
        int lm = q * 4;
        hdnf[lm + 0][n] = tanhf(s.x);
        hdnf[lm + 1][n] = tanhf(s.y);
        hdnf[lm + 2][n] = tanhf(s.z);
        hdnf[lm + 3][n] = tanhf(s.w);
    }
    if (tid < 32) hdnf[tid][17] = 0.f;
    __syncthreads();

    for (int idx = tid; idx < 32 * 9; idx += 256) {
        int lm = idx / 9, j = idx % 9;
        g_hdnp[h][m0 + lm][j] = pack2(hdnf[lm][2 * j], hdnf[lm][2 * j + 1]);
    }
}

// ================= Kernel C2 (fused): logits + softmax + att@f conv-acc + epilogue =================
// grid 8 (head) x 512 thr. Dynamic smem.
// layout: hdnp_s [256][10] u64 (20480) | W2s [256*17] f (17408) | patt [16][17][20] f (21760)
//         | att [17][17] f (1156+pad) | attw [289] u64 (2312)
#define C2_OFF_W2   20480
#define C2_OFF_PATT (20480 + 17408)
#define C2_OFF_ATT  (C2_OFF_PATT + 21760)
#define C2_OFF_ATTW (C2_OFF_ATT + 1184)
#define C2_SMEM     (C2_OFF_ATTW + 2312)
__global__ void __launch_bounds__(512) kC2(const float* __restrict__ W2,
                                           const float* __restrict__ b2,
                                           const float* __restrict__ conv_w,
                                           const float* __restrict__ conv_b,
                                           const float* __restrict__ Xs,
                                           const float* __restrict__ ROIs,
                                           float* __restrict__ out, int out_size) {
    extern __shared__ __align__(16) char sm[];
    u64*   hdnp_s = reinterpret_cast<u64*>(sm);                    // [m*10 + j]
    float* W2s    = reinterpret_cast<float*>(sm + C2_OFF_W2);      // [m*17 + k]
    float* patt   = reinterpret_cast<float*>(sm + C2_OFF_PATT);    // [mq*340 + n*20 + k]
    float* att    = reinterpret_cast<float*>(sm + C2_OFF_ATT);     // [k*17 + n]
    u64*   attw   = reinterpret_cast<u64*>(sm + C2_OFF_ATTW);      // [k*17 + n]
    __shared__ int sflag;

    const int h = blockIdx.x, tid = threadIdx.x;

    // stage hdn (packed) and W2 (coalesced float4)
    for (int idx = tid; idx < MM * 9; idx += 512) {
        int m = idx / 9, j = idx % 9;
        hdnp_s[m * 10 + j] = g_hdnp[h][m][j];
    }
    {
        const float4* w2g = reinterpret_cast<const float4*>(W2 + (size_t)h * MM * NN);
        float4* w2s4 = reinterpret_cast<float4*>(W2s);
        for (int idx = tid; idx < MM * NN / 4; idx += 512)
            w2s4[idx] = w2g[idx];
    }
    __syncthreads();

    // phase 2: logits = hdn @ W2; warp mq covers 16 m's, lane = k (from smem)
    {
        const int mq = tid >> 5, lane = tid & 31;
        if (lane < NN) {
            u64 acc2[9];
#pragma unroll
            for (int j = 0; j < 9; ++j) acc2[j] = 0ull;
#pragma unroll
            for (int mm = 0; mm < 16; ++mm) {
                const int m = mq * 16 + mm;
                u64 w2 = dup2(W2s[m * NN + lane]);
                const ulonglong2* row = reinterpret_cast<const ulonglong2*>(&hdnp_s[m * 10]);
#pragma unroll
                for (int j = 0; j < 4; ++j) {
                    ulonglong2 q = row[j];
                    ffma2(acc2[2 * j],     q.x, w2);
                    ffma2(acc2[2 * j + 1], q.y, w2);
                }
                ffma2(acc2[8], hdnp_s[m * 10 + 8], w2);
            }
#pragma unroll
            for (int j = 0; j < 9; ++j) {
                float2 v = unpack2(acc2[j]);
                patt[mq * 340 + (2 * j) * 20 + lane] = v.x;
                if (2 * j + 1 < NN) patt[mq * 340 + (2 * j + 1) * 20 + lane] = v.y;
            }
        }
    }
    __syncthreads();

    for (int idx = tid; idx < NN * NN; idx += 512) {
        int n = idx / NN, k = idx % NN;
        float s = b2[h * NN + k];
#pragma unroll
        for (int q = 0; q < 16; ++q) s += patt[q * 340 + n * 20 + k];
        att[k * NN + n] = s;
    }
    __syncthreads();

    // phase 3: softmax over n, premultiply conv_w
    if (tid < NN) {
        const int k = tid;
        float mx = -1e30f;
#pragma unroll
        for (int n = 0; n < NN; ++n) mx = fmaxf(mx, att[k * NN + n]);
        float ex[NN], sum = 0.f;
#pragma unroll
        for (int n = 0; n < NN; ++n) { ex[n] = expf(att[k * NN + n] - mx); sum += ex[n]; }
        float scale = conv_w[h] / sum;
#pragma unroll
        for (int n = 0; n < NN; ++n) attw[k * NN + n] = dup2(ex[n] * scale);
    }
    __syncthreads();

    // phase 4: this head's conv contribution -> atomic accumulate into g_out
    {
        const int ng  = tid >> 8;        // 0: n 0..8, 1: n 9..16
        const int dp  = tid & 255;       // d-pair index
        const int nlo = ng ? 9 : 0, nhi = ng ? 17 : 9;

        u64 acc[NN];
#pragma unroll
        for (int k = 0; k < NN; ++k) acc[k] = 0ull;

        for (int n = nlo; n < nhi; ++n) {
            u64 f2 = *reinterpret_cast<const u64*>(&g_f[h][n][2 * dp]);
#pragma unroll
            for (int k = 0; k < NN; ++k)
                ffma2(acc[k], attw[k * NN + n], f2);
        }
#pragma unroll
        for (int k = 0; k < NN; ++k) {
            float2 v = unpack2(acc[k]);
            atomicAdd(&g_out[k * DD + 2 * dp],     v.x);
            atomicAdd(&g_out[k * DD + 2 * dp + 1], v.y);
        }
    }

    // last-block epilogue
    __threadfence();
    __syncthreads();
    if (tid == 0) sflag = (atomicAdd(&g_ctr, 1) == HH - 1);
    __syncthreads();
    if (sflag) {
        const float cb = conv_b[0];
        volatile float* go = g_out;
        for (int idx = tid; idx < NN * DD; idx += 512) {
            float v = go[idx];
            out[idx] = fmaxf(v + cb, 0.f) + Xs[idx];
            g_out[idx] = 0.f;                       // reset for next replay
        }
        if (tid < NN * 3 && out_size >= NN * DD + NN * 3)
            out[NN * DD + tid] = ROIs[tid];
        if (tid == 0) g_ctr = 0;
    }
}

// ---------------- launch ----------------
extern "C" void kernel_launch(void* const* d_in, const int* in_sizes, int n_in,
                              void* d_out, int out_size) {
    const float *Xs = 0, *ROIs = 0, *FC = 0, *W1 = 0, *b1 = 0, *W2 = 0, *b2 = 0,
                *cw = 0, *cb = 0;
    for (int i = 0; i < n_in; ++i) {
        const float* p = (const float*)d_in[i];
        switch (in_sizes[i]) {
            case NN * DD:       Xs = p; break;
            case NN * 3:        ROIs = p; break;
            case NN * NN:       /* adj */ break;
            case HH * DD * DD:  FC = p; break;
            case HH * CIN * MM: W1 = p; break;
            case HH * MM:       b1 = p; break;
            case HH * MM * NN:  W2 = p; break;
            case HH * NN:       b2 = p; break;
            case HH:            cw = p; break;
            case 1:             cb = p; break;
            default: break;
        }
    }
    float* out = (float*)d_out;

    static bool attr_done = false;
    if (!attr_done) {
        cudaFuncSetAttribute(kC2, cudaFuncAttributeMaxDynamicSharedMemorySize, C2_SMEM);
        attr_done = true;
    }

    kA<<<dim3(32, 2, 8), 256>>>(Xs, FC);
    kB<<<dim3(64, 8), 256>>>(ROIs, W1);
    kC1<<<dim3(8, 8), 256>>>(b1);
    kC2<<<HH, 512, C2_SMEM>>>(W2, b2, cw, cb, Xs, ROIs, out, out_size);
}

// round 10
// speedup vs baseline: 1.0615x; 1.0615x over previous
#include <cuda_runtime.h>
#include <math.h>

#define NN 17
#define DD 512
#define HH 8
#define MM 256
#define CIN 515

typedef unsigned long long u64;

// ---------------- f32x2 helpers ----------------
__device__ __forceinline__ void ffma2(u64& acc, u64 a, u64 b) {
    asm("fma.rn.f32x2 %0, %1, %2, %0;" : "+l"(acc) : "l"(a), "l"(b));
}
__device__ __forceinline__ u64 dup2(float x) {
    u64 r; asm("mov.b64 %0, {%1, %1};" : "=l"(r) : "f"(x)); return r;
}
__device__ __forceinline__ u64 pack2(float x, float y) {
    u64 r; asm("mov.b64 %0, {%1, %2};" : "=l"(r) : "f"(x), "f"(y)); return r;
}
__device__ __forceinline__ float2 unpack2(u64 a) {
    float2 f; asm("mov.b64 {%0, %1}, %2;" : "=f"(f.x), "=f"(f.y) : "l"(a)); return f;
}

// ---------------- device scratch ----------------
__device__ float g_pA[32][HH][NN][DD];   // Xs@FC partials, 32 d-chunks (16 wide)
__device__ float g_f[HH][NN][DD];        // f = relu(Xs@FC)
__device__ float g_pB[64][HH][NN][MM];   // cat@W1 partials, 64 c-chunks (8 wide)
__device__ u64   g_hdnp[HH][MM][9];      // tanh hidden, dup-pair packed [m][(n,n+1)]
__device__ u64   g_attw[HH][NN * NN];    // dup pairs conv_w*softmax, [h][k*17+n]

// ================= Kernel A: partial f = Xs @ FC =================
// grid (dc=32, ec=2, h=8) = 512 blocks x 256 thr.
// Group g = tid>>7: g0 computes n 0..8, g1 computes n 9..16 (same e-pairs).
__global__ void __launch_bounds__(256) kA(const float* __restrict__ Xs,
                                          const float* __restrict__ FC) {
    const int dc = blockIdx.x, ec = blockIdx.y, h = blockIdx.z, tid = threadIdx.x;
    const int d0 = dc * 16;
    const int g = tid >> 7;
    const int P = ec * 128 + (tid & 127);   // e-pair index

    __shared__ __align__(16) u64 xsd[2][16][10];   // dup pairs [grp][dd][slot]
    for (int idx = tid; idx < 16 * 20; idx += 256) {
        int dd = idx / 20, s = idx % 20;
        int gg = s / 10, j = s % 10;
        int n = gg ? 9 + j : j;
        bool ok = gg ? (j < 8) : (j < 9);
        float v = ok ? Xs[n * DD + d0 + dd] : 0.f;
        xsd[gg][dd][j] = dup2(v);
    }
    __syncthreads();

    u64 acc[10];
#pragma unroll
    for (int j = 0; j < 10; ++j) acc[j] = 0ull;

    const u64* fc = reinterpret_cast<const u64*>(FC)
                  + (size_t)h * 131072 + (size_t)d0 * 256 + P;
    u64 buf[8];
#pragma unroll
    for (int p = 0; p < 8; ++p) buf[p] = fc[(size_t)p * 256];

#pragma unroll
    for (int dd = 0; dd < 16; ++dd) {
        u64 w = buf[dd & 7];
        if (dd < 8) buf[dd & 7] = fc[(size_t)(dd + 8) * 256];
        const ulonglong2* row = reinterpret_cast<const ulonglong2*>(&xsd[g][dd][0]);
#pragma unroll
        for (int j = 0; j < 5; ++j) {
            ulonglong2 q = row[j];
            ffma2(acc[2 * j],     q.x, w);
            ffma2(acc[2 * j + 1], q.y, w);
        }
    }
    if (g == 0) {
#pragma unroll
        for (int j = 0; j < 9; ++j)
            *reinterpret_cast<u64*>(&g_pA[dc][h][j][2 * P]) = acc[j];
    } else {
#pragma unroll
        for (int j = 0; j < 8; ++j)
            *reinterpret_cast<u64*>(&g_pA[dc][h][9 + j][2 * P]) = acc[j];
    }
}

// ================= Kernel B: reduce f chunk + relu, partial cat @ W1 =================
// grid (cc=64, h=8) = 512 blocks x 256 thr. Group split over n like kA.
// cc==63 additionally handles the 3 coordinate rows.
__global__ void __launch_bounds__(256) kB(const float* __restrict__ ROIs,
                                          const float* __restrict__ W1) {
    const int cc = blockIdx.x, h = blockIdx.y, tid = threadIdx.x;
    const int c0 = cc * 8;
    const int g = tid >> 7;
    const int mp = tid & 127;   // m-pair

    __shared__ __align__(16) u64 catd[2][11][10];   // rows 0..7 c, 8..10 coords

    for (int idx = tid; idx < 2 * 11 * 10; idx += 256)
        reinterpret_cast<u64*>(catd)[idx] = 0ull;
    __syncthreads();

    if (tid < NN * 8) {
        int n = tid >> 3, cp = tid & 7;
        float v = 0.f;
#pragma unroll
        for (int s = 0; s < 32; ++s) v += g_pA[s][h][n][c0 + cp];
        v = fmaxf(v, 0.f);
        g_f[h][n][c0 + cp] = v;
        if (n < 9) catd[0][cp][n] = dup2(v);
        else       catd[1][cp][n - 9] = dup2(v);
    }
    if (cc == 63 && tid < NN * 3) {
        int n = tid / 3, jj = tid % 3;
        float v = ROIs[tid];
        if (n < 9) catd[0][8 + jj][n] = dup2(v);
        else       catd[1][8 + jj][n - 9] = dup2(v);
    }
    __syncthreads();

    u64 acc[10];
#pragma unroll
    for (int j = 0; j < 10; ++j) acc[j] = 0ull;

    const u64* w1 = reinterpret_cast<const u64*>(W1)
                  + (size_t)h * 65920 + (size_t)c0 * 128 + mp;
    u64 buf[8];
#pragma unroll
    for (int p = 0; p < 8; ++p) buf[p] = w1[(size_t)p * 128];

#pragma unroll
    for (int i = 0; i < 8; ++i) {
        u64 w = buf[i];
        const ulonglong2* row = reinterpret_cast<const ulonglong2*>(&catd[g][i][0]);
#pragma unroll
        for (int j = 0; j < 5; ++j) {
            ulonglong2 q = row[j];
            ffma2(acc[2 * j],     q.x, w);
            ffma2(acc[2 * j + 1], q.y, w);
        }
    }
    if (cc == 63) {
#pragma unroll
        for (int jj = 0; jj < 3; ++jj) {
            u64 w = reinterpret_cast<const u64*>(W1)[(size_t)h * 65920 + (size_t)(DD + jj) * 128 + mp];
            const ulonglong2* row = reinterpret_cast<const ulonglong2*>(&catd[g][8 + jj][0]);
#pragma unroll
            for (int j = 0; j < 5; ++j) {
                ulonglong2 q = row[j];
                ffma2(acc[2 * j],     q.x, w);
                ffma2(acc[2 * j + 1], q.y, w);
            }
        }
    }
    if (g == 0) {
#pragma unroll
        for (int j = 0; j < 9; ++j)
            *reinterpret_cast<u64*>(&g_pB[cc][h][j][2 * mp]) = acc[j];
    } else {
#pragma unroll
        for (int j = 0; j < 8; ++j)
            *reinterpret_cast<u64*>(&g_pB[cc][h][9 + j][2 * mp]) = acc[j];
    }
}

// ================= Kernel C1: reduce g_pB + bias + tanh -> packed g_hdnp =================
// grid (mc=8, h=8) = 64 blocks x 256 thr; block handles 32 m's of head h.
__global__ void __launch_bounds__(256) kC1(const float* __restrict__ b1) {
    const int mc = blockIdx.x, h = blockIdx.y, tid = threadIdx.x;
    const int m0 = mc * 32;

    __shared__ float hdnf[32][20];   // [local m][n], col 17 = pad

    if (tid < NN * 8) {
        int n = tid >> 3, q = tid & 7;
        int m4 = m0 + q * 4;
        float4 s = *reinterpret_cast<const float4*>(b1 + h * MM + m4);
#pragma unroll
        for (int cc = 0; cc < 64; ++cc) {
            float4 v = *reinterpret_cast<const float4*>(&g_pB[cc][h][n][m4]);
            s.x += v.x; s.y += v.y; s.z += v.z; s.w += v.w;
        }
        int lm = q * 4;
        hdnf[lm + 0][n] = tanhf(s.x);
        hdnf[lm + 1][n] = tanhf(s.y);
        hdnf[lm + 2][n] = tanhf(s.z);
        hdnf[lm + 3][n] = tanhf(s.w);
    }
    if (tid < 32) hdnf[tid][17] = 0.f;
    __syncthreads();

    for (int idx = tid; idx < 32 * 9; idx += 256) {
        int lm = idx / 9, j = idx % 9;
        g_hdnp[h][m0 + lm][j] = pack2(hdnf[lm][2 * j], hdnf[lm][2 * j + 1]);
    }
}

// ================= Kernel C2: logits = hdn @ W2 (smem-staged), softmax, premult conv_w =================
// grid 8 (head) x 512 thr. Dynamic smem:
// hdnp_s [256][10] u64 (20480) | W2s [256*17] f (17408) | patt [16][17][20] f (21760) | att (1184)
#define C2_OFF_W2   20480
#define C2_OFF_PATT (20480 + 17408)
#define C2_OFF_ATT  (C2_OFF_PATT + 21760)
#define C2_SMEM     (C2_OFF_ATT + 1184)
__global__ void __launch_bounds__(512) kC2(const float* __restrict__ W2,
                                           const float* __restrict__ b2,
                                           const float* __restrict__ conv_w) {
    extern __shared__ __align__(16) char sm[];
    u64*   hdnp_s = reinterpret_cast<u64*>(sm);                    // [m*10 + j]
    float* W2s    = reinterpret_cast<float*>(sm + C2_OFF_W2);      // [m*17 + k]
    float* patt   = reinterpret_cast<float*>(sm + C2_OFF_PATT);    // [mq*340 + n*20 + k]
    float* att    = reinterpret_cast<float*>(sm + C2_OFF_ATT);     // [k*17 + n]

    const int h = blockIdx.x, tid = threadIdx.x;

    // stage hdn (packed) and W2 (coalesced float4)
    for (int idx = tid; idx < MM * 9; idx += 512) {
        int m = idx / 9, j = idx % 9;
        hdnp_s[m * 10 + j] = g_hdnp[h][m][j];
    }
    {
        const float4* w2g = reinterpret_cast<const float4*>(W2 + (size_t)h * MM * NN);
        float4* w2s4 = reinterpret_cast<float4*>(W2s);
        for (int idx = tid; idx < MM * NN / 4; idx += 512)
            w2s4[idx] = w2g[idx];
    }
    __syncthreads();

    // logits = hdn @ W2; warp mq covers 16 m's, lane = k (all operands in smem)
    {
        const int mq = tid >> 5, lane = tid & 31;
        if (lane < NN) {
            u64 acc2[9];
#pragma unroll
            for (int j = 0; j < 9; ++j) acc2[j] = 0ull;
#pragma unroll
            for (int mm = 0; mm < 16; ++mm) {
                const int m = mq * 16 + mm;
                u64 w2 = dup2(W2s[m * NN + lane]);
                const ulonglong2* row = reinterpret_cast<const ulonglong2*>(&hdnp_s[m * 10]);
#pragma unroll
                for (int j = 0; j < 4; ++j) {
                    ulonglong2 q = row[j];
                    ffma2(acc2[2 * j],     q.x, w2);
                    ffma2(acc2[2 * j + 1], q.y, w2);
                }
                ffma2(acc2[8], hdnp_s[m * 10 + 8], w2);
            }
#pragma unroll
            for (int j = 0; j < 9; ++j) {
                float2 v = unpack2(acc2[j]);
                patt[mq * 340 + (2 * j) * 20 + lane] = v.x;
                if (2 * j + 1 < NN) patt[mq * 340 + (2 * j + 1) * 20 + lane] = v.y;
            }
        }
    }
    __syncthreads();

    for (int idx = tid; idx < NN * NN; idx += 512) {
        int n = idx / NN, k = idx % NN;
        float s = b2[h * NN + k];
#pragma unroll
        for (int q = 0; q < 16; ++q) s += patt[q * 340 + n * 20 + k];
        att[k * NN + n] = s;
    }
    __syncthreads();

    // softmax over n, premultiply conv_w
    if (tid < NN) {
        const int k = tid;
        float mx = -1e30f;
#pragma unroll
        for (int n = 0; n < NN; ++n) mx = fmaxf(mx, att[k * NN + n]);
        float ex[NN], sum = 0.f;
#pragma unroll
        for (int n = 0; n < NN; ++n) { ex[n] = expf(att[k * NN + n] - mx); sum += ex[n]; }
        float scale = conv_w[h] / sum;
#pragma unroll
        for (int n = 0; n < NN; ++n) g_attw[h][k * NN + n] = dup2(ex[n] * scale);
    }
}

// ================= Kernel C3: out = relu(sum_{h,n} attw*f + cb) + Xs =================
// grid (k=17, ec=2) = 34 blocks x 256 thr. Group hg = tid>>7 covers 4 heads.
__global__ void __launch_bounds__(256) kC3(const float* __restrict__ Xs,
                                           const float* __restrict__ ROIs,
                                           const float* __restrict__ conv_b,
                                           float* __restrict__ out, int out_size) {
    const int k = blockIdx.x, ec = blockIdx.y, tid = threadIdx.x;
    const int hg = tid >> 7, dt = tid & 127;
    const int P = ec * 128 + dt;   // e-pair

    __shared__ u64 aw[HH][NN];
    __shared__ float2 part[128];

    if (tid < HH * NN)
        aw[tid / NN][tid % NN] = g_attw[tid / NN][k * NN + tid % NN];
    __syncthreads();

    const u64* fb = reinterpret_cast<const u64*>(g_f) + P;
    const int hb = hg * 4;

    u64 acc[4];
#pragma unroll
    for (int j = 0; j < 4; ++j) acc[j] = 0ull;

#pragma unroll
    for (int hh = 0; hh < 4; ++hh) {
        const int h = hb + hh;
#pragma unroll
        for (int n = 0; n < NN; ++n) {
            u64 f2 = fb[(size_t)(h * NN + n) * 256];
            ffma2(acc[(hh * NN + n) & 3], aw[h][n], f2);
        }
    }
    float2 a0 = unpack2(acc[0]), a1 = unpack2(acc[1]);
    float2 a2 = unpack2(acc[2]), a3 = unpack2(acc[3]);
    float2 s = make_float2(a0.x + a1.x + a2.x + a3.x,
                           a0.y + a1.y + a2.y + a3.y);
    if (hg == 1) part[dt] = s;
    __syncthreads();
    if (hg == 0) {
        const float cb = conv_b[0];
        float rx = s.x + part[dt].x + cb;
        float ry = s.y + part[dt].y + cb;
        const float2 xv = *reinterpret_cast<const float2*>(Xs + k * DD + 2 * P);
        float2 r = make_float2(fmaxf(rx, 0.f) + xv.x, fmaxf(ry, 0.f) + xv.y);
        *reinterpret_cast<float2*>(out + k * DD + 2 * P) = r;
    }

    if (k == 0 && ec == 0 && tid < NN * 3 && out_size >= NN * DD + NN * 3)
        out[NN * DD + tid] = ROIs[tid];
}

// ---------------- launch ----------------
extern "C" void kernel_launch(void* const* d_in, const int* in_sizes, int n_in,
                              void* d_out, int out_size) {
    const float *Xs = 0, *ROIs = 0, *FC = 0, *W1 = 0, *b1 = 0, *W2 = 0, *b2 = 0,
                *cw = 0, *cb = 0;
    for (int i = 0; i < n_in; ++i) {
        const float* p = (const float*)d_in[i];
        switch (in_sizes[i]) {
            case NN * DD:       Xs = p; break;
            case NN * 3:        ROIs = p; break;
            case NN * NN:       /* adj */ break;
            case HH * DD * DD:  FC = p; break;
            case HH * CIN * MM: W1 = p; break;
            case HH * MM:       b1 = p; break;
            case HH * MM * NN:  W2 = p; break;
            case HH * NN:       b2 = p; break;
            case HH:            cw = p; break;
            case 1:             cb = p; break;
            default: break;
        }
    }
    float* out = (float*)d_out;

    static bool attr_done = false;
    if (!attr_done) {
        cudaFuncSetAttribute(kC2, cudaFuncAttributeMaxDynamicSharedMemorySize, C2_SMEM);
        attr_done = true;
    }

    kA<<<dim3(32, 2, 8), 256>>>(Xs, FC);
    kB<<<dim3(64, 8), 256>>>(ROIs, W1);
    kC1<<<dim3(8, 8), 256>>>(b1);
    kC2<<<HH, 512, C2_SMEM>>>(W2, b2, cw);
    kC3<<<dim3(NN, 2), 256>>>(Xs, ROIs, cb, out, out_size);
}

// round 11
// speedup vs baseline: 1.3034x; 1.2279x over previous
#include <cuda_runtime.h>
#include <math.h>

#define NN 17
#define DD 512
#define HH 8
#define MM 256
#define CIN 515
#define NB 256          // grid size; co-resident (2/SM * 148 = 296 >= 256)

typedef unsigned long long u64;

// ---------------- f32x2 helpers ----------------
__device__ __forceinline__ void ffma2(u64& acc, u64 a, u64 b) {
    asm("fma.rn.f32x2 %0, %1, %2, %0;" : "+l"(acc) : "l"(a), "l"(b));
}
__device__ __forceinline__ u64 dup2(float x) {
    u64 r; asm("mov.b64 %0, {%1, %1};" : "=l"(r) : "f"(x)); return r;
}
__device__ __forceinline__ u64 pack2(float x, float y) {
    u64 r; asm("mov.b64 %0, {%1, %2};" : "=l"(r) : "f"(x), "f"(y)); return r;
}
__device__ __forceinline__ float2 unpack2(u64 a) {
    float2 f; asm("mov.b64 {%0, %1}, %2;" : "=f"(f.x), "=f"(f.y) : "l"(a)); return f;
}

// ---------------- device scratch ----------------
__device__ float g_pA[16][HH][NN][DD];   // Xs@FC partials, 16 d-chunks (32 wide)
__device__ float g_f[HH][NN][DD];        // f = relu(Xs@FC)
__device__ float g_pB[32][HH][NN][MM];   // cat@W1 partials, 32 c-chunks (16 wide)
__device__ u64   g_hdnp[HH][MM][9];      // tanh hidden, dup-pair packed
__device__ u64   g_attw[HH][NN * NN];    // dup pairs conv_w*softmax, [h][k*17+n]

// ---------------- device-wide barrier (replay-safe, monotonic release) ----------------
__device__ int g_cnt[4];
__device__ volatile unsigned g_rel[4];

__device__ __forceinline__ void gbar(int b) {
    __syncthreads();
    if (threadIdx.x == 0) {
        __threadfence();
        unsigned r0 = g_rel[b];
        if (atomicAdd(&g_cnt[b], 1) == NB - 1) {
            g_cnt[b] = 0;            // reset for next replay (ordered before release)
            __threadfence();
            g_rel[b] = r0 + 1;       // release (monotonic; never reset)
        } else {
            while (g_rel[b] == r0) __nanosleep(64);
        }
        __threadfence();
    }
    __syncthreads();
}

// ================= The one persistent kernel =================
// smem union (max user = phase C2: 20480 + 10880 + 1184 = 32544 B)
#define SM_BYTES 32544
__global__ void __launch_bounds__(256, 2)
mega(const float* __restrict__ Xs, const float* __restrict__ ROIs,
     const float* __restrict__ FC, const float* __restrict__ W1,
     const float* __restrict__ b1, const float* __restrict__ W2,
     const float* __restrict__ b2, const float* __restrict__ conv_w,
     const float* __restrict__ conv_b, float* __restrict__ out, int out_size) {
    __shared__ __align__(16) char smbuf[SM_BYTES];
    const int bid = blockIdx.x, tid = threadIdx.x;

    // ======== Phase A: partial f = Xs @ FC ========
    // bid = dc(16) | ec(1bit) | h(3bit); 32-wide d-chunks; group g over n.
    {
        const int dc = bid & 15, ec = (bid >> 4) & 1, h = bid >> 5;
        const int d0 = dc * 32;
        const int g = tid >> 7;
        const int P = ec * 128 + (tid & 127);   // e-pair

        u64* xsd = reinterpret_cast<u64*>(smbuf);   // [g][dd][slot] = (g*32+dd)*10+j
        for (int idx = tid; idx < 32 * 20; idx += 256) {
            int dd = idx / 20, s = idx % 20;
            int gg = s / 10, j = s % 10;
            int n = gg ? 9 + j : j;
            bool ok = gg ? (j < 8) : (j < 9);
            float v = ok ? Xs[n * DD + d0 + dd] : 0.f;
            xsd[(gg * 32 + dd) * 10 + j] = dup2(v);
        }
        __syncthreads();

        u64 acc[10];
#pragma unroll
        for (int j = 0; j < 10; ++j) acc[j] = 0ull;

        const u64* fc = reinterpret_cast<const u64*>(FC)
                      + (size_t)h * 131072 + (size_t)d0 * 256 + P;
        u64 buf[8];
#pragma unroll
        for (int p = 0; p < 8; ++p) buf[p] = fc[(size_t)p * 256];

#pragma unroll
        for (int dd = 0; dd < 32; ++dd) {
            u64 w = buf[dd & 7];
            if (dd < 24) buf[dd & 7] = fc[(size_t)(dd + 8) * 256];
            const ulonglong2* row = reinterpret_cast<const ulonglong2*>(&xsd[(g * 32 + dd) * 10]);
#pragma unroll
            for (int j = 0; j < 5; ++j) {
                ulonglong2 q = row[j];
                ffma2(acc[2 * j],     q.x, w);
                ffma2(acc[2 * j + 1], q.y, w);
            }
        }
        if (g == 0) {
#pragma unroll
            for (int j = 0; j < 9; ++j)
                *reinterpret_cast<u64*>(&g_pA[dc][h][j][2 * P]) = acc[j];
        } else {
#pragma unroll
            for (int j = 0; j < 8; ++j)
                *reinterpret_cast<u64*>(&g_pA[dc][h][9 + j][2 * P]) = acc[j];
        }
    }
    gbar(0);

    // ======== Phase B: reduce f chunk + relu, partial cat @ W1 ========
    // bid = cc(32) | h(3bit); 16-wide c-chunks; cc==31 also coords.
    {
        const int cc = bid & 31, h = bid >> 5;
        const int c0 = cc * 16;
        const int g = tid >> 7;
        const int mp = tid & 127;   // m-pair

        u64* catd = reinterpret_cast<u64*>(smbuf);   // [g][row(19)][slot10]
        for (int idx = tid; idx < 2 * 19 * 10; idx += 256) catd[idx] = 0ull;
        __syncthreads();

        for (int idx = tid; idx < NN * 16; idx += 256) {
            int n = idx >> 4, cp = idx & 15;
            float v = 0.f;
#pragma unroll
            for (int s = 0; s < 16; ++s) v += g_pA[s][h][n][c0 + cp];
            v = fmaxf(v, 0.f);
            g_f[h][n][c0 + cp] = v;
            if (n < 9) catd[(0 * 19 + cp) * 10 + n] = dup2(v);
            else       catd[(1 * 19 + cp) * 10 + (n - 9)] = dup2(v);
        }
        if (cc == 31 && tid < NN * 3) {
            int n = tid / 3, jj = tid % 3;
            float v = ROIs[tid];
            if (n < 9) catd[(0 * 19 + 16 + jj) * 10 + n] = dup2(v);
            else       catd[(1 * 19 + 16 + jj) * 10 + (n - 9)] = dup2(v);
        }
        __syncthreads();

        u64 acc[10];
#pragma unroll
        for (int j = 0; j < 10; ++j) acc[j] = 0ull;

        const u64* w1 = reinterpret_cast<const u64*>(W1)
                      + (size_t)h * 65920 + (size_t)c0 * 128 + mp;
        u64 buf[8];
#pragma unroll
        for (int p = 0; p < 8; ++p) buf[p] = w1[(size_t)p * 128];

#pragma unroll
        for (int i = 0; i < 16; ++i) {
            u64 w = buf[i & 7];
            if (i < 8) buf[i & 7] = w1[(size_t)(i + 8) * 128];
            const ulonglong2* row = reinterpret_cast<const ulonglong2*>(&catd[(g * 19 + i) * 10]);
#pragma unroll
            for (int j = 0; j < 5; ++j) {
                ulonglong2 q = row[j];
                ffma2(acc[2 * j],     q.x, w);
                ffma2(acc[2 * j + 1], q.y, w);
            }
        }
        if (cc == 31) {
#pragma unroll
            for (int jj = 0; jj < 3; ++jj) {
                u64 w = reinterpret_cast<const u64*>(W1)[(size_t)h * 65920 + (size_t)(DD + jj) * 128 + mp];
                const ulonglong2* row = reinterpret_cast<const ulonglong2*>(&catd[(g * 19 + 16 + jj) * 10]);
#pragma unroll
                for (int j = 0; j < 5; ++j) {
                    ulonglong2 q = row[j];
                    ffma2(acc[2 * j],     q.x, w);
                    ffma2(acc[2 * j + 1], q.y, w);
                }
            }
        }
        if (g == 0) {
#pragma unroll
            for (int j = 0; j < 9; ++j)
                *reinterpret_cast<u64*>(&g_pB[cc][h][j][2 * mp]) = acc[j];
        } else {
#pragma unroll
            for (int j = 0; j < 8; ++j)
                *reinterpret_cast<u64*>(&g_pB[cc][h][9 + j][2 * mp]) = acc[j];
        }
    }
    gbar(1);

    // ======== Phase C1: reduce g_pB + bias + tanh -> packed g_hdnp ========
    // blocks 0..63: mc = bid&7, h = bid>>3; 32 m's each.
    if (bid < 64) {
        const int mc = bid & 7, h = bid >> 3;
        const int m0 = mc * 32;
        float* hdnf = reinterpret_cast<float*>(smbuf);   // [lm][20]

        if (tid < NN * 8) {
            int n = tid >> 3, q = tid & 7;
            int m4 = m0 + q * 4;
            float4 s = *reinterpret_cast<const float4*>(b1 + h * MM + m4);
#pragma unroll
            for (int cc = 0; cc < 32; ++cc) {
                float4 v = *reinterpret_cast<const float4*>(&g_pB[cc][h][n][m4]);
                s.x += v.x; s.y += v.y; s.z += v.z; s.w += v.w;
            }
            int lm = q * 4;
            hdnf[(lm + 0) * 20 + n] = tanhf(s.x);
            hdnf[(lm + 1) * 20 + n] = tanhf(s.y);
            hdnf[(lm + 2) * 20 + n] = tanhf(s.z);
            hdnf[(lm + 3) * 20 + n] = tanhf(s.w);
        }
        if (tid < 32) hdnf[tid * 20 + 17] = 0.f;
        __syncthreads();

        for (int idx = tid; idx < 32 * 9; idx += 256) {
            int lm = idx / 9, j = idx % 9;
            g_hdnp[h][m0 + lm][j] = pack2(hdnf[lm * 20 + 2 * j], hdnf[lm * 20 + 2 * j + 1]);
        }
    }
    gbar(2);

    // ======== Phase C2: logits = hdn @ W2, softmax, premult conv_w ========
    // blocks 0..7 = h. smem: hdnp_s [256*10] u64 | patt [8][17][20] f | att [289] f
    if (bid < 8) {
        const int h = bid;
        u64*   hdnp_s = reinterpret_cast<u64*>(smbuf);                 // 20480 B
        float* patt   = reinterpret_cast<float*>(smbuf + 20480);       // 10880 B
        float* att    = reinterpret_cast<float*>(smbuf + 20480 + 10880); // 1156 B

        for (int idx = tid; idx < MM * 9; idx += 256) {
            int m = idx / 9, j = idx % 9;
            hdnp_s[m * 10 + j] = g_hdnp[h][m][j];
        }
        __syncthreads();

        {
            const int mq = tid >> 5, lane = tid & 31;   // 8 warps x 32 m's
            if (lane < NN) {
                u64 acc2[9];
#pragma unroll
                for (int j = 0; j < 9; ++j) acc2[j] = 0ull;
#pragma unroll
                for (int mm = 0; mm < 32; ++mm) {
                    const int m = mq * 32 + mm;
                    u64 w2 = dup2(__ldg(&W2[((size_t)h * MM + m) * NN + lane]));
                    const ulonglong2* row = reinterpret_cast<const ulonglong2*>(&hdnp_s[m * 10]);
#pragma unroll
                    for (int j = 0; j < 4; ++j) {
                        ulonglong2 q = row[j];
                        ffma2(acc2[2 * j],     q.x, w2);
                        ffma2(acc2[2 * j + 1], q.y, w2);
                    }
                    ffma2(acc2[8], hdnp_s[m * 10 + 8], w2);
                }
#pragma unroll
                for (int j = 0; j < 9; ++j) {
                    float2 v = unpack2(acc2[j]);
                    patt[mq * 340 + (2 * j) * 20 + lane] = v.x;
                    if (2 * j + 1 < NN) patt[mq * 340 + (2 * j + 1) * 20 + lane] = v.y;
                }
            }
        }
        __syncthreads();

        for (int idx = tid; idx < NN * NN; idx += 256) {
            int n = idx / NN, k = idx % NN;
            float s = b2[h * NN + k];
#pragma unroll
            for (int q = 0; q < 8; ++q) s += patt[q * 340 + n * 20 + k];
            att[k * NN + n] = s;
        }
        __syncthreads();

        if (tid < NN) {
            const int k = tid;
            float mx = -1e30f;
#pragma unroll
            for (int n = 0; n < NN; ++n) mx = fmaxf(mx, att[k * NN + n]);
            float ex[NN], sum = 0.f;
#pragma unroll
            for (int n = 0; n < NN; ++n) { ex[n] = expf(att[k * NN + n] - mx); sum += ex[n]; }
            float scale = conv_w[h] / sum;
#pragma unroll
            for (int n = 0; n < NN; ++n) g_attw[h][k * NN + n] = dup2(ex[n] * scale);
        }
    }
    gbar(3);

    // ======== Phase C3: out = relu(sum_{h,n} attw*f + cb) + Xs ========
    // blocks 0..33: k = bid>>1, ec = bid&1; group hg over heads.
    if (bid < 2 * NN) {
        const int k = bid >> 1, ec = bid & 1;
        const int hg = tid >> 7, dt = tid & 127;
        const int P = ec * 128 + dt;

        u64*    aw   = reinterpret_cast<u64*>(smbuf);           // [h*17+n], 1088 B
        float2* part = reinterpret_cast<float2*>(smbuf + 1088); // [128]

        if (tid < HH * NN)
            aw[tid] = g_attw[tid / NN][k * NN + tid % NN];
        __syncthreads();

        const u64* fb = reinterpret_cast<const u64*>(g_f) + P;
        const int hb = hg * 4;

        u64 acc[4];
#pragma unroll
        for (int j = 0; j < 4; ++j) acc[j] = 0ull;

#pragma unroll
        for (int hh = 0; hh < 4; ++hh) {
            const int h = hb + hh;
#pragma unroll
            for (int n = 0; n < NN; ++n) {
                u64 f2 = fb[(size_t)(h * NN + n) * 256];
                ffma2(acc[(hh * NN + n) & 3], aw[h * NN + n], f2);
            }
        }
        float2 a0 = unpack2(acc[0]), a1 = unpack2(acc[1]);
        float2 a2 = unpack2(acc[2]), a3 = unpack2(acc[3]);
        float2 s = make_float2(a0.x + a1.x + a2.x + a3.x,
                               a0.y + a1.y + a2.y + a3.y);
        if (hg == 1) part[dt] = s;
        __syncthreads();
        if (hg == 0) {
            const float cb = conv_b[0];
            float rx = s.x + part[dt].x + cb;
            float ry = s.y + part[dt].y + cb;
            const float2 xv = *reinterpret_cast<const float2*>(Xs + k * DD + 2 * P);
            float2 r = make_float2(fmaxf(rx, 0.f) + xv.x, fmaxf(ry, 0.f) + xv.y);
            *reinterpret_cast<float2*>(out + k * DD + 2 * P) = r;
        }
        if (k == 0 && ec == 0 && tid < NN * 3 && out_size >= NN * DD + NN * 3)
            out[NN * DD + tid] = ROIs[tid];
    }
}

// ---------------- launch ----------------
extern "C" void kernel_launch(void* const* d_in, const int* in_sizes, int n_in,
                              void* d_out, int out_size) {
    const float *Xs = 0, *ROIs = 0, *FC = 0, *W1 = 0, *b1 = 0, *W2 = 0, *b2 = 0,
                *cw = 0, *cb = 0;
    for (int i = 0; i < n_in; ++i) {
        const float* p = (const float*)d_in[i];
        switch (in_sizes[i]) {
            case NN * DD:       Xs = p; break;
            case NN * 3:        ROIs = p; break;
            case NN * NN:       /* adj */ break;
            case HH * DD * DD:  FC = p; break;
            case HH * CIN * MM: W1 = p; break;
            case HH * MM:       b1 = p; break;
            case HH * MM * NN:  W2 = p; break;
            case HH * NN:       b2 = p; break;
            case HH:            cw = p; break;
            case 1:             cb = p; break;
            default: break;
        }
    }
    float* out = (float*)d_out;

    mega<<<NB, 256>>>(Xs, ROIs, FC, W1, b1, W2, b2, cw, cb, out, out_size);
}

// round 12
// speedup vs baseline: 1.4100x; 1.0817x over previous
#include <cuda_runtime.h>
#include <math.h>

#define NN 17
#define DD 512
#define HH 8
#define MM 256
#define CIN 515
#define NB 256          // grid size; co-resident (2/SM * 148 = 296 >= 256)

typedef unsigned long long u64;

// ---------------- f32x2 helpers ----------------
__device__ __forceinline__ void ffma2(u64& acc, u64 a, u64 b) {
    asm("fma.rn.f32x2 %0, %1, %2, %0;" : "+l"(acc) : "l"(a), "l"(b));
}
__device__ __forceinline__ u64 dup2(float x) {
    u64 r; asm("mov.b64 %0, {%1, %1};" : "=l"(r) : "f"(x)); return r;
}
__device__ __forceinline__ float2 unpack2(u64 a) {
    float2 f; asm("mov.b64 {%0, %1}, %2;" : "=f"(f.x), "=f"(f.y) : "l"(a)); return f;
}

// ---------------- device scratch ----------------
__device__ float g_pA[16][HH][NN][DD];   // Xs@FC partials, 16 d-chunks (32 wide)
__device__ float g_f[HH][NN][DD];        // f = relu(Xs@FC)
__device__ float g_pB[32][HH][NN][MM];   // cat@W1 partials, 32 c-chunks (16 wide)
__device__ float g_patt[HH][8][NN * NN]; // partial logits per m-chunk [h][mc][n*17+k]
__device__ u64   g_attw[HH][NN * NN];    // dup pairs conv_w*softmax, [h][k*17+n]

// ---------------- device-wide barrier (replay-safe, monotonic release) ----------------
__device__ int g_cnt[4];
__device__ volatile unsigned g_rel[4];

__device__ __forceinline__ void gbar(int b) {
    __syncthreads();
    if (threadIdx.x == 0) {
        __threadfence();
        unsigned r0 = g_rel[b];
        if (atomicAdd(&g_cnt[b], 1) == NB - 1) {
            g_cnt[b] = 0;            // reset for next replay (ordered before release)
            __threadfence();
            g_rel[b] = r0 + 1;       // release (monotonic; never reset)
        } else {
            while (g_rel[b] == r0) __nanosleep(64);
        }
        __threadfence();
    }
    __syncthreads();
}

// ================= The one persistent kernel =================
// smem union: phase A 5120 B | phase B 3040 B | phase C1 2560+2176+4 B | C2 1156 B | C3 2112 B
#define SM_BYTES 12800
__global__ void __launch_bounds__(256, 2)
mega(const float* __restrict__ Xs, const float* __restrict__ ROIs,
     const float* __restrict__ FC, const float* __restrict__ W1,
     const float* __restrict__ b1, const float* __restrict__ W2,
     const float* __restrict__ b2, const float* __restrict__ conv_w,
     const float* __restrict__ conv_b, float* __restrict__ out, int out_size) {
    __shared__ __align__(16) char smbuf[SM_BYTES];
    const int bid = blockIdx.x, tid = threadIdx.x;

    // ======== Phase A: partial f = Xs @ FC ========
    // bid = dc(16) | ec(1bit) | h(3bit); 32-wide d-chunks; group g over n.
    {
        const int dc = bid & 15, ec = (bid >> 4) & 1, h = bid >> 5;
        const int d0 = dc * 32;
        const int g = tid >> 7;
        const int P = ec * 128 + (tid & 127);   // e-pair

        u64* xsd = reinterpret_cast<u64*>(smbuf);   // [(g*32+dd)*10 + j]
        for (int idx = tid; idx < 32 * 20; idx += 256) {
            int dd = idx / 20, s = idx % 20;
            int gg = s / 10, j = s % 10;
            int n = gg ? 9 + j : j;
            bool ok = gg ? (j < 8) : (j < 9);
            float v = ok ? Xs[n * DD + d0 + dd] : 0.f;
            xsd[(gg * 32 + dd) * 10 + j] = dup2(v);
        }
        __syncthreads();

        u64 acc[10];
#pragma unroll
        for (int j = 0; j < 10; ++j) acc[j] = 0ull;

        const u64* fc = reinterpret_cast<const u64*>(FC)
                      + (size_t)h * 131072 + (size_t)d0 * 256 + P;
        u64 buf[8];
#pragma unroll
        for (int p = 0; p < 8; ++p) buf[p] = fc[(size_t)p * 256];

#pragma unroll
        for (int dd = 0; dd < 32; ++dd) {
            u64 w = buf[dd & 7];
            if (dd < 24) buf[dd & 7] = fc[(size_t)(dd + 8) * 256];
            const ulonglong2* row = reinterpret_cast<const ulonglong2*>(&xsd[(g * 32 + dd) * 10]);
#pragma unroll
            for (int j = 0; j < 5; ++j) {
                ulonglong2 q = row[j];
                ffma2(acc[2 * j],     q.x, w);
                ffma2(acc[2 * j + 1], q.y, w);
            }
        }
        if (g == 0) {
#pragma unroll
            for (int j = 0; j < 9; ++j)
                *reinterpret_cast<u64*>(&g_pA[dc][h][j][2 * P]) = acc[j];
        } else {
#pragma unroll
            for (int j = 0; j < 8; ++j)
                *reinterpret_cast<u64*>(&g_pA[dc][h][9 + j][2 * P]) = acc[j];
        }
    }
    gbar(0);

    // ======== Phase B: reduce f chunk + relu, partial cat @ W1 ========
    // bid = cc(32) | h(3bit); 16-wide c-chunks; cc==31 also coords.
    {
        const int cc = bid & 31, h = bid >> 5;
        const int c0 = cc * 16;
        const int g = tid >> 7;
        const int mp = tid & 127;   // m-pair

        u64* catd = reinterpret_cast<u64*>(smbuf);   // [(g*19+row)*10 + slot]
        for (int idx = tid; idx < 2 * 19 * 10; idx += 256) catd[idx] = 0ull;
        __syncthreads();

        for (int idx = tid; idx < NN * 16; idx += 256) {
            int n = idx >> 4, cp = idx & 15;
            float v = 0.f;
#pragma unroll
            for (int s = 0; s < 16; ++s) v += g_pA[s][h][n][c0 + cp];
            v = fmaxf(v, 0.f);
            g_f[h][n][c0 + cp] = v;
            if (n < 9) catd[(0 * 19 + cp) * 10 + n] = dup2(v);
            else       catd[(1 * 19 + cp) * 10 + (n - 9)] = dup2(v);
        }
        if (cc == 31 && tid < NN * 3) {
            int n = tid / 3, jj = tid % 3;
            float v = ROIs[tid];
            if (n < 9) catd[(0 * 19 + 16 + jj) * 10 + n] = dup2(v);
            else       catd[(1 * 19 + 16 + jj) * 10 + (n - 9)] = dup2(v);
        }
        __syncthreads();

        u64 acc[10];
#pragma unroll
        for (int j = 0; j < 10; ++j) acc[j] = 0ull;

        const u64* w1 = reinterpret_cast<const u64*>(W1)
                      + (size_t)h * 65920 + (size_t)c0 * 128 + mp;
        u64 buf[8];
#pragma unroll
        for (int p = 0; p < 8; ++p) buf[p] = w1[(size_t)p * 128];

#pragma unroll
        for (int i = 0; i < 16; ++i) {
            u64 w = buf[i & 7];
            if (i < 8) buf[i & 7] = w1[(size_t)(i + 8) * 128];
            const ulonglong2* row = reinterpret_cast<const ulonglong2*>(&catd[(g * 19 + i) * 10]);
#pragma unroll
            for (int j = 0; j < 5; ++j) {
                ulonglong2 q = row[j];
                ffma2(acc[2 * j],     q.x, w);
                ffma2(acc[2 * j + 1], q.y, w);
            }
        }
        if (cc == 31) {
#pragma unroll
            for (int jj = 0; jj < 3; ++jj) {
                u64 w = reinterpret_cast<const u64*>(W1)[(size_t)h * 65920 + (size_t)(DD + jj) * 128 + mp];
                const ulonglong2* row = reinterpret_cast<const ulonglong2*>(&catd[(g * 19 + 16 + jj) * 10]);
#pragma unroll
                for (int j = 0; j < 5; ++j) {
                    ulonglong2 q = row[j];
                    ffma2(acc[2 * j],     q.x, w);
                    ffma2(acc[2 * j + 1], q.y, w);
                }
            }
        }
        if (g == 0) {
#pragma unroll
            for (int j = 0; j < 9; ++j)
                *reinterpret_cast<u64*>(&g_pB[cc][h][j][2 * mp]) = acc[j];
        } else {
#pragma unroll
            for (int j = 0; j < 8; ++j)
                *reinterpret_cast<u64*>(&g_pB[cc][h][9 + j][2 * mp]) = acc[j];
        }
    }
    gbar(1);

    // ======== Phase C1: reduce g_pB + bias + tanh + PARTIAL LOGITS ========
    // blocks 0..63: mc = bid&7, h = bid>>3; 32 m's each.
    // smem: hdnf [32][20] f (2560) | W2s [32*17] f (2176)
    if (bid < 64) {
        const int mc = bid & 7, h = bid >> 3;
        const int m0 = mc * 32;
        float* hdnf = reinterpret_cast<float*>(smbuf);            // [lm*20 + n]
        float* W2s  = reinterpret_cast<float*>(smbuf + 2560);     // [lm*17 + k]

        if (tid < NN * 8) {
            int n = tid >> 3, q = tid & 7;
            int m4 = m0 + q * 4;
            float4 s = *reinterpret_cast<const float4*>(b1 + h * MM + m4);
#pragma unroll
            for (int cc = 0; cc < 32; ++cc) {
                float4 v = *reinterpret_cast<const float4*>(&g_pB[cc][h][n][m4]);
                s.x += v.x; s.y += v.y; s.z += v.z; s.w += v.w;
            }
            int lm = q * 4;
            hdnf[(lm + 0) * 20 + n] = tanhf(s.x);
            hdnf[(lm + 1) * 20 + n] = tanhf(s.y);
            hdnf[(lm + 2) * 20 + n] = tanhf(s.z);
            hdnf[(lm + 3) * 20 + n] = tanhf(s.w);
        }
        // stage W2 slab [m0..m0+32) x 17, coalesced float4 (544 floats = 136 ld)
        if (tid < 136) {
            reinterpret_cast<float4*>(W2s)[tid] =
                reinterpret_cast<const float4*>(W2 + ((size_t)h * MM + m0) * NN)[tid];
        }
        __syncthreads();

        // partial logits: patt[n][k] = sum_lm hdnf[lm][n] * W2s[lm][k]
        for (int idx = tid; idx < NN * NN; idx += 256) {
            int n = idx / NN, k = idx % NN;
            float s = 0.f;
#pragma unroll
            for (int lm = 0; lm < 32; ++lm)
                s = fmaf(hdnf[lm * 20 + n], W2s[lm * NN + k], s);
            g_patt[h][mc][idx] = s;
        }
    }
    gbar(2);

    // ======== Phase C2: reduce partials + bias, softmax, premult conv_w ========
    // blocks 0..7 = h. smem: att [289] f
    if (bid < 8) {
        const int h = bid;
        float* att = reinterpret_cast<float*>(smbuf);   // [k*17 + n]

        for (int idx = tid; idx < NN * NN; idx += 256) {
            int n = idx / NN, k = idx % NN;
            float s = b2[h * NN + k];
#pragma unroll
            for (int q = 0; q < 8; ++q) s += g_patt[h][q][idx];
            att[k * NN + n] = s;
        }
        __syncthreads();

        if (tid < NN) {
            const int k = tid;
            float mx = -1e30f;
#pragma unroll
            for (int n = 0; n < NN; ++n) mx = fmaxf(mx, att[k * NN + n]);
            float ex[NN], sum = 0.f;
#pragma unroll
            for (int n = 0; n < NN; ++n) { ex[n] = expf(att[k * NN + n] - mx); sum += ex[n]; }
            float scale = conv_w[h] / sum;
#pragma unroll
            for (int n = 0; n < NN; ++n) g_attw[h][k * NN + n] = dup2(ex[n] * scale);
        }
    }
    gbar(3);

    // ======== Phase C3: out = relu(sum_{h,n} attw*f + cb) + Xs ========
    // blocks 0..33: k = bid>>1, ec = bid&1; group hg over heads.
    if (bid < 2 * NN) {
        const int k = bid >> 1, ec = bid & 1;
        const int hg = tid >> 7, dt = tid & 127;
        const int P = ec * 128 + dt;

        u64*    aw   = reinterpret_cast<u64*>(smbuf);           // [h*17+n], 1088 B
        float2* part = reinterpret_cast<float2*>(smbuf + 1088); // [128]

        if (tid < HH * NN)
            aw[tid] = g_attw[tid / NN][k * NN + tid % NN];
        __syncthreads();

        const u64* fb = reinterpret_cast<const u64*>(g_f) + P;
        const int hb = hg * 4;

        u64 acc[4];
#pragma unroll
        for (int j = 0; j < 4; ++j) acc[j] = 0ull;

#pragma unroll
        for (int hh = 0; hh < 4; ++hh) {
            const int h = hb + hh;
#pragma unroll
            for (int n = 0; n < NN; ++n) {
                u64 f2 = fb[(size_t)(h * NN + n) * 256];
                ffma2(acc[(hh * NN + n) & 3], aw[h * NN + n], f2);
            }
        }
        float2 a0 = unpack2(acc[0]), a1 = unpack2(acc[1]);
        float2 a2 = unpack2(acc[2]), a3 = unpack2(acc[3]);
        float2 s = make_float2(a0.x + a1.x + a2.x + a3.x,
                               a0.y + a1.y + a2.y + a3.y);
        if (hg == 1) part[dt] = s;
        __syncthreads();
        if (hg == 0) {
            const float cb = conv_b[0];
            float rx = s.x + part[dt].x + cb;
            float ry = s.y + part[dt].y + cb;
            const float2 xv = *reinterpret_cast<const float2*>(Xs + k * DD + 2 * P);
            float2 r = make_float2(fmaxf(rx, 0.f) + xv.x, fmaxf(ry, 0.f) + xv.y);
            *reinterpret_cast<float2*>(out + k * DD + 2 * P) = r;
        }
        if (k == 0 && ec == 0 && tid < NN * 3 && out_size >= NN * DD + NN * 3)
            out[NN * DD + tid] = ROIs[tid];
    }
}

// ---------------- launch ----------------
extern "C" void kernel_launch(void* const* d_in, const int* in_sizes, int n_in,
                              void* d_out, int out_size) {
    const float *Xs = 0, *ROIs = 0, *FC = 0, *W1 = 0, *b1 = 0, *W2 = 0, *b2 = 0,
                *cw = 0, *cb = 0;
    for (int i = 0; i < n_in; ++i) {
        const float* p = (const float*)d_in[i];
        switch (in_sizes[i]) {
            case NN * DD:       Xs = p; break;
            case NN * 3:        ROIs = p; break;
            case NN * NN:       /* adj */ break;
            case HH * DD * DD:  FC = p; break;
            case HH * CIN * MM: W1 = p; break;
            case HH * MM:       b1 = p; break;
            case HH * MM * NN:  W2 = p; break;
            case HH * NN:       b2 = p; break;
            case HH:            cw = p; break;
            case 1:             cb = p; break;
            default: break;
        }
    }
    float* out = (float*)d_out;

    mega<<<NB, 256>>>(Xs, ROIs, FC, W1, b1, W2, b2, cw, cb, out, out_size);
}